// round 1
// baseline (speedup 1.0000x reference)
#include <cuda_runtime.h>
#include <math.h>

// Problem constants
constexpr int BATCH = 8;
constexpr int SEQ   = 2048;
constexpr int DIM   = 1024;
constexpr float EPS = 1e-5f;

// ---------------------------------------------------------------------------
// Scratch (device globals — no allocations allowed)
// ---------------------------------------------------------------------------
__device__ float g_q    [(size_t)BATCH * SEQ * DIM];
__device__ float g_k    [(size_t)BATCH * SEQ * DIM];
__device__ float g_v    [(size_t)BATCH * SEQ * DIM];
__device__ float g_sc   [(size_t)BATCH * SEQ * SEQ];   // scores -> softmax weights (in place)
__device__ float g_attn [(size_t)BATCH * SEQ * DIM];
__device__ float g_post [(size_t)BATCH * SEQ * DIM];
__device__ float g_h    [(size_t)BATCH * SEQ * DIM];

// ---------------------------------------------------------------------------
// Block reductions (256 threads)
// ---------------------------------------------------------------------------
__device__ __forceinline__ float blk_red_sum(float v, float* sh) {
    #pragma unroll
    for (int o = 16; o > 0; o >>= 1) v += __shfl_xor_sync(0xffffffffu, v, o);
    __syncthreads();
    if ((threadIdx.x & 31) == 0) sh[threadIdx.x >> 5] = v;
    __syncthreads();
    float r = sh[0];
    #pragma unroll
    for (int w = 1; w < 8; w++) r += sh[w];
    return r;
}

__device__ __forceinline__ float blk_red_max(float v, float* sh) {
    #pragma unroll
    for (int o = 16; o > 0; o >>= 1) v = fmaxf(v, __shfl_xor_sync(0xffffffffu, v, o));
    __syncthreads();
    if ((threadIdx.x & 31) == 0) sh[threadIdx.x >> 5] = v;
    __syncthreads();
    float r = sh[0];
    #pragma unroll
    for (int w = 1; w < 8; w++) r = fmaxf(r, sh[w]);
    return r;
}

// ---------------------------------------------------------------------------
// GEMM NT: C = alpha * A @ B^T (+ bias).  A:[M,K] rm, B:[N,K] rm, C:[M,N] rm.
// Batched via blockIdx.z with element strides sA/sB/sC.
// Tile 128x128x16, 256 threads, 8x8 per thread.
// Requires M%128==0, N%128==0, K%16==0 (true for all our shapes).
// ---------------------------------------------------------------------------
template<bool HAS_BIAS>
__global__ void __launch_bounds__(256) gemm_nt_kernel(
    const float* __restrict__ A, const float* __restrict__ B,
    const float* __restrict__ bias, float* __restrict__ C,
    int M, int N, int K, float alpha,
    size_t sA, size_t sB, size_t sC)
{
    constexpr int BM = 128, BN = 128, BK = 16, TM = 8, TN = 8;
    A += (size_t)blockIdx.z * sA;
    B += (size_t)blockIdx.z * sB;
    C += (size_t)blockIdx.z * sC;

    __shared__ float As[BK][BM];
    __shared__ float Bs[BK][BN];

    const int tid = threadIdx.x;
    const int tx  = tid & 15;          // 0..15 (N direction)
    const int ty  = tid >> 4;          // 0..15 (M direction)
    const int row0 = blockIdx.y * BM;
    const int col0 = blockIdx.x * BN;

    const int lr = tid >> 2;           // 0..63
    const int lc = (tid & 3) * 4;      // 0,4,8,12

    const float* Aload = A + (size_t)row0 * K;
    const float* Bload = B + (size_t)col0 * K;

    float acc[TM][TN] = {};

    for (int kt = 0; kt < K; kt += BK) {
        #pragma unroll
        for (int r = 0; r < 2; r++) {
            const int rr = lr + r * 64;
            float4 va = *reinterpret_cast<const float4*>(Aload + (size_t)rr * K + kt + lc);
            As[lc + 0][rr] = va.x; As[lc + 1][rr] = va.y;
            As[lc + 2][rr] = va.z; As[lc + 3][rr] = va.w;
            float4 vb = *reinterpret_cast<const float4*>(Bload + (size_t)rr * K + kt + lc);
            Bs[lc + 0][rr] = vb.x; Bs[lc + 1][rr] = vb.y;
            Bs[lc + 2][rr] = vb.z; Bs[lc + 3][rr] = vb.w;
        }
        __syncthreads();

        #pragma unroll
        for (int kk = 0; kk < BK; kk++) {
            float ra[TM], rb[TN];
            *reinterpret_cast<float4*>(&ra[0]) = *reinterpret_cast<const float4*>(&As[kk][ty * TM + 0]);
            *reinterpret_cast<float4*>(&ra[4]) = *reinterpret_cast<const float4*>(&As[kk][ty * TM + 4]);
            *reinterpret_cast<float4*>(&rb[0]) = *reinterpret_cast<const float4*>(&Bs[kk][tx * TN + 0]);
            *reinterpret_cast<float4*>(&rb[4]) = *reinterpret_cast<const float4*>(&Bs[kk][tx * TN + 4]);
            #pragma unroll
            for (int i = 0; i < TM; i++)
                #pragma unroll
                for (int j = 0; j < TN; j++)
                    acc[i][j] = fmaf(ra[i], rb[j], acc[i][j]);
        }
        __syncthreads();
    }

    float bv[TN];
    if (HAS_BIAS) {
        #pragma unroll
        for (int j = 0; j < TN; j++) bv[j] = bias[col0 + tx * TN + j];
    }

    #pragma unroll
    for (int i = 0; i < TM; i++) {
        const int m = row0 + ty * TM + i;
        float4* Cp = reinterpret_cast<float4*>(C + (size_t)m * N + col0 + tx * TN);
        #pragma unroll
        for (int jj = 0; jj < 2; jj++) {
            float4 o;
            const int j0 = jj * 4;
            o.x = acc[i][j0 + 0] * alpha;
            o.y = acc[i][j0 + 1] * alpha;
            o.z = acc[i][j0 + 2] * alpha;
            o.w = acc[i][j0 + 3] * alpha;
            if (HAS_BIAS) { o.x += bv[j0 + 0]; o.y += bv[j0 + 1]; o.z += bv[j0 + 2]; o.w += bv[j0 + 3]; }
            Cp[jj] = o;
        }
    }
}

// ---------------------------------------------------------------------------
// GEMM NN: C = A @ B.  A:[M,K] rm, B:[K,N] rm, C:[M,N] rm. Batched via blockIdx.z.
// ---------------------------------------------------------------------------
__global__ void __launch_bounds__(256) gemm_nn_kernel(
    const float* __restrict__ A, const float* __restrict__ B,
    float* __restrict__ C,
    int M, int N, int K,
    size_t sA, size_t sB, size_t sC)
{
    constexpr int BM = 128, BN = 128, BK = 16, TM = 8, TN = 8;
    A += (size_t)blockIdx.z * sA;
    B += (size_t)blockIdx.z * sB;
    C += (size_t)blockIdx.z * sC;

    __shared__ float As[BK][BM];
    __shared__ float Bs[BK][BN];

    const int tid = threadIdx.x;
    const int tx  = tid & 15;
    const int ty  = tid >> 4;
    const int row0 = blockIdx.y * BM;
    const int col0 = blockIdx.x * BN;

    // A loader (transpose into smem)
    const int lr = tid >> 2;           // 0..63
    const int lc = (tid & 3) * 4;      // 0,4,8,12
    // B loader (direct copy)
    const int br = tid >> 5;           // 0..7
    const int bc = (tid & 31) * 4;     // 0..124

    const float* Aload = A + (size_t)row0 * K;

    float acc[TM][TN] = {};

    for (int kt = 0; kt < K; kt += BK) {
        #pragma unroll
        for (int r = 0; r < 2; r++) {
            const int rr = lr + r * 64;
            float4 va = *reinterpret_cast<const float4*>(Aload + (size_t)rr * K + kt + lc);
            As[lc + 0][rr] = va.x; As[lc + 1][rr] = va.y;
            As[lc + 2][rr] = va.z; As[lc + 3][rr] = va.w;
        }
        #pragma unroll
        for (int r = 0; r < 2; r++) {
            const int rr = br + r * 8;
            float4 vb = *reinterpret_cast<const float4*>(B + (size_t)(kt + rr) * N + col0 + bc);
            *reinterpret_cast<float4*>(&Bs[rr][bc]) = vb;
        }
        __syncthreads();

        #pragma unroll
        for (int kk = 0; kk < BK; kk++) {
            float ra[TM], rb[TN];
            *reinterpret_cast<float4*>(&ra[0]) = *reinterpret_cast<const float4*>(&As[kk][ty * TM + 0]);
            *reinterpret_cast<float4*>(&ra[4]) = *reinterpret_cast<const float4*>(&As[kk][ty * TM + 4]);
            *reinterpret_cast<float4*>(&rb[0]) = *reinterpret_cast<const float4*>(&Bs[kk][tx * TN + 0]);
            *reinterpret_cast<float4*>(&rb[4]) = *reinterpret_cast<const float4*>(&Bs[kk][tx * TN + 4]);
            #pragma unroll
            for (int i = 0; i < TM; i++)
                #pragma unroll
                for (int j = 0; j < TN; j++)
                    acc[i][j] = fmaf(ra[i], rb[j], acc[i][j]);
        }
        __syncthreads();
    }

    #pragma unroll
    for (int i = 0; i < TM; i++) {
        const int m = row0 + ty * TM + i;
        float4* Cp = reinterpret_cast<float4*>(C + (size_t)m * N + col0 + tx * TN);
        #pragma unroll
        for (int jj = 0; jj < 2; jj++) {
            float4 o;
            const int j0 = jj * 4;
            o.x = acc[i][j0 + 0]; o.y = acc[i][j0 + 1];
            o.z = acc[i][j0 + 2]; o.w = acc[i][j0 + 3];
            Cp[jj] = o;
        }
    }
}

// ---------------------------------------------------------------------------
// Masked softmax over rows of scores [B, S, S], in place.
// Keys j >= lengths[b] are excluded (exact zeros), matching -inf masking.
// ---------------------------------------------------------------------------
__global__ void __launch_bounds__(256) softmax_kernel(
    float* __restrict__ scores, const int* __restrict__ lengths)
{
    const int b = blockIdx.y;
    const int i = blockIdx.x;
    const int len = lengths[b];
    float* row = scores + ((size_t)b * SEQ + i) * SEQ;
    const int tid = threadIdx.x;
    __shared__ float sh[8];

    float m = -INFINITY;
    for (int j = tid; j < len; j += 256) m = fmaxf(m, row[j]);
    m = blk_red_max(m, sh);

    float s = 0.f;
    for (int j = tid; j < len; j += 256) {
        float e = __expf(row[j] - m);
        row[j] = e;
        s += e;
    }
    s = blk_red_sum(s, sh);
    const float inv = 1.f / s;

    for (int j = tid; j < SEQ; j += 256) {
        row[j] = (j < len) ? row[j] * inv : 0.f;
    }
}

// ---------------------------------------------------------------------------
// out = LayerNorm( f(x1) + x2 ) * g + b,  f = identity or ReLU.
// One block per row (DIM = 1024, 256 threads * float4).
// ---------------------------------------------------------------------------
template<bool RELU>
__global__ void __launch_bounds__(256) add_ln_kernel(
    const float* __restrict__ x1, const float* __restrict__ x2,
    const float* __restrict__ g, const float* __restrict__ bvec,
    float* __restrict__ out)
{
    const size_t row = blockIdx.x;
    const int tid = threadIdx.x;
    __shared__ float sh[8];

    float4 a = reinterpret_cast<const float4*>(x1 + row * DIM)[tid];
    float4 c = reinterpret_cast<const float4*>(x2 + row * DIM)[tid];
    if (RELU) {
        a.x = fmaxf(a.x, 0.f); a.y = fmaxf(a.y, 0.f);
        a.z = fmaxf(a.z, 0.f); a.w = fmaxf(a.w, 0.f);
    }
    float x0 = a.x + c.x, x1v = a.y + c.y, x2v = a.z + c.z, x3 = a.w + c.w;

    float s = x0 + x1v + x2v + x3;
    s = blk_red_sum(s, sh);
    const float mean = s * (1.f / DIM);

    float d0 = x0 - mean, d1 = x1v - mean, d2 = x2v - mean, d3 = x3 - mean;
    float sq = d0 * d0 + d1 * d1 + d2 * d2 + d3 * d3;
    sq = blk_red_sum(sq, sh);
    const float rstd = rsqrtf(sq * (1.f / DIM) + EPS);

    float4 gv = reinterpret_cast<const float4*>(g)[tid];
    float4 bv = reinterpret_cast<const float4*>(bvec)[tid];
    float4 o;
    o.x = d0 * rstd * gv.x + bv.x;
    o.y = d1 * rstd * gv.y + bv.y;
    o.z = d2 * rstd * gv.z + bv.z;
    o.w = d3 * rstd * gv.w + bv.w;
    reinterpret_cast<float4*>(out + row * DIM)[tid] = o;
}

// ---------------------------------------------------------------------------
// Launch
// ---------------------------------------------------------------------------
extern "C" void kernel_launch(void* const* d_in, const int* in_sizes, int n_in,
                              void* d_out, int out_size)
{
    const float* seq     = (const float*)d_in[0];
    const int*   lengths = (const int*)  d_in[1];
    const float* Wq = (const float*)d_in[2];  const float* bq = (const float*)d_in[3];
    const float* Wk = (const float*)d_in[4];  const float* bk = (const float*)d_in[5];
    const float* Wv = (const float*)d_in[6];  const float* bv = (const float*)d_in[7];
    const float* Wo = (const float*)d_in[8];  const float* bo = (const float*)d_in[9];
    const float* g1 = (const float*)d_in[10]; const float* b1 = (const float*)d_in[11];
    const float* g2 = (const float*)d_in[12]; const float* b2 = (const float*)d_in[13];
    float* out = (float*)d_out;

    float *q, *k, *v, *sc, *attn, *post, *h;
    cudaGetSymbolAddress((void**)&q,    g_q);
    cudaGetSymbolAddress((void**)&k,    g_k);
    cudaGetSymbolAddress((void**)&v,    g_v);
    cudaGetSymbolAddress((void**)&sc,   g_sc);
    cudaGetSymbolAddress((void**)&attn, g_attn);
    cudaGetSymbolAddress((void**)&post, g_post);
    cudaGetSymbolAddress((void**)&h,    g_h);

    const int M  = BATCH * SEQ;           // 16384
    const size_t sBD = (size_t)SEQ * DIM; // per-batch stride for [S,D]
    const size_t sSS = (size_t)SEQ * SEQ; // per-batch stride for [S,S]

    dim3 blk(256);

    // 1) Q, K, V projections: [16384,1024] = seq @ W^T + b
    dim3 gproj(DIM / 128, M / 128, 1);
    gemm_nt_kernel<true><<<gproj, blk>>>(seq, Wq, bq, q, M, DIM, DIM, 1.f, 0, 0, 0);
    gemm_nt_kernel<true><<<gproj, blk>>>(seq, Wk, bk, k, M, DIM, DIM, 1.f, 0, 0, 0);
    gemm_nt_kernel<true><<<gproj, blk>>>(seq, Wv, bv, v, M, DIM, DIM, 1.f, 0, 0, 0);

    // 2) scores = q @ k^T / sqrt(D)   per batch
    dim3 gsc(SEQ / 128, SEQ / 128, BATCH);
    gemm_nt_kernel<false><<<gsc, blk>>>(q, k, nullptr, sc, SEQ, SEQ, DIM,
                                        1.f / 32.f, sBD, sBD, sSS);

    // 3) masked softmax (in place)
    dim3 gsm(SEQ, BATCH);
    softmax_kernel<<<gsm, blk>>>(sc, lengths);

    // 4) attn = w @ v   per batch
    dim3 gav(DIM / 128, SEQ / 128, BATCH);
    gemm_nn_kernel<<<gav, blk>>>(sc, v, attn, SEQ, DIM, SEQ, sSS, sBD, sBD);

    // 5) post = LN(seq + attn)
    add_ln_kernel<false><<<M, blk>>>(attn, seq, g1, b1, post);

    // 6) h = post @ Wo^T + bo
    gemm_nt_kernel<true><<<gproj, blk>>>(post, Wo, bo, h, M, DIM, DIM, 1.f, 0, 0, 0);

    // 7) out = LN(relu(h) + post)
    add_ln_kernel<true><<<M, blk>>>(h, post, g2, b2, out);
}

// round 3
// speedup vs baseline: 2.1631x; 2.1631x over previous
#include <cuda_runtime.h>
#include <cuda_bf16.h>
#include <math.h>
#include <stdint.h>

// Problem constants
constexpr int BATCH = 8;
constexpr int SEQ   = 2048;
constexpr int DIM   = 1024;
constexpr float EPS = 1e-5f;

// ---------------------------------------------------------------------------
// Scratch (device globals — no allocations allowed)
// ---------------------------------------------------------------------------
__device__ __align__(256) float g_q   [(size_t)BATCH * SEQ * DIM];   // unused slot kept small? (q fp32 not needed)
__device__ __align__(256) float g_v   [(size_t)BATCH * SEQ * DIM];
__device__ __align__(256) float g_sc  [(size_t)BATCH * SEQ * SEQ];
__device__ __align__(256) float g_attn[(size_t)BATCH * SEQ * DIM];
__device__ __align__(256) float g_post[(size_t)BATCH * SEQ * DIM];
__device__ __align__(256) float g_h   [(size_t)BATCH * SEQ * DIM];

// split (hi/lo bf16) operand buffers
__device__ __align__(256) __nv_bfloat16 g_seq_h[(size_t)BATCH*SEQ*DIM], g_seq_l[(size_t)BATCH*SEQ*DIM];
__device__ __align__(256) __nv_bfloat16 g_Wq_h[(size_t)DIM*DIM], g_Wq_l[(size_t)DIM*DIM];
__device__ __align__(256) __nv_bfloat16 g_Wk_h[(size_t)DIM*DIM], g_Wk_l[(size_t)DIM*DIM];
__device__ __align__(256) __nv_bfloat16 g_Wv_h[(size_t)DIM*DIM], g_Wv_l[(size_t)DIM*DIM];
__device__ __align__(256) __nv_bfloat16 g_Wo_h[(size_t)DIM*DIM], g_Wo_l[(size_t)DIM*DIM];
__device__ __align__(256) __nv_bfloat16 g_q_h [(size_t)BATCH*SEQ*DIM], g_q_l [(size_t)BATCH*SEQ*DIM];
__device__ __align__(256) __nv_bfloat16 g_k_h [(size_t)BATCH*SEQ*DIM], g_k_l [(size_t)BATCH*SEQ*DIM];
__device__ __align__(256) __nv_bfloat16 g_vT_h[(size_t)BATCH*DIM*SEQ], g_vT_l[(size_t)BATCH*DIM*SEQ];
__device__ __align__(256) __nv_bfloat16 g_sc_h[(size_t)BATCH*SEQ*SEQ], g_sc_l[(size_t)BATCH*SEQ*SEQ];
__device__ __align__(256) __nv_bfloat16 g_post_h[(size_t)BATCH*SEQ*DIM], g_post_l[(size_t)BATCH*SEQ*DIM];

// ---------------------------------------------------------------------------
// PTX helpers (compute_80-safe: cp.async, ldmatrix, mma.sync)
// ---------------------------------------------------------------------------
__device__ __forceinline__ uint32_t smem_to_u32(const void* p) {
    uint32_t a;
    asm("{ .reg .u64 t; cvta.to.shared.u64 t, %1; cvt.u32.u64 %0, t; }" : "=r"(a) : "l"(p));
    return a;
}
__device__ __forceinline__ void cp_async16(uint32_t s, const void* g) {
    asm volatile("cp.async.cg.shared.global [%0], [%1], 16;" :: "r"(s), "l"(g));
}
__device__ __forceinline__ void cp_commit() { asm volatile("cp.async.commit_group;" ::: "memory"); }
template<int N> __device__ __forceinline__ void cp_wait() {
    asm volatile("cp.async.wait_group %0;" :: "n"(N) : "memory");
}
__device__ __forceinline__ void ldsm_x4(uint32_t* r, uint32_t a) {
    asm volatile("ldmatrix.sync.aligned.m8n8.x4.shared.b16 {%0,%1,%2,%3}, [%4];"
                 : "=r"(r[0]), "=r"(r[1]), "=r"(r[2]), "=r"(r[3]) : "r"(a));
}
__device__ __forceinline__ void ldsm_x2(uint32_t* r, uint32_t a) {
    asm volatile("ldmatrix.sync.aligned.m8n8.x2.shared.b16 {%0,%1}, [%2];"
                 : "=r"(r[0]), "=r"(r[1]) : "r"(a));
}
__device__ __forceinline__ void mma16816(float* d, const uint32_t* a, const uint32_t* b) {
    asm volatile(
        "mma.sync.aligned.m16n8k16.row.col.f32.bf16.bf16.f32 "
        "{%0,%1,%2,%3}, {%4,%5,%6,%7}, {%8,%9}, {%0,%1,%2,%3};"
        : "+f"(d[0]), "+f"(d[1]), "+f"(d[2]), "+f"(d[3])
        : "r"(a[0]), "r"(a[1]), "r"(a[2]), "r"(a[3]), "r"(b[0]), "r"(b[1]));
}

__device__ __forceinline__ void split2(float x, __nv_bfloat16& h, __nv_bfloat16& l) {
    h = __float2bfloat16_rn(x);
    l = __float2bfloat16_rn(x - __bfloat162float(h));
}

// ---------------------------------------------------------------------------
// HMMA GEMM NT: C = alpha * A @ B^T (+ bias), A:[M,K] hi/lo bf16, B:[N,K] hi/lo.
// Block 128x128, 8 warps (4m x 2n), warp tile 32x64, BK=32, 3-stage cp.async.
// ---------------------------------------------------------------------------
constexpr int BK       = 32;
constexpr int LDS_ROW  = 80;                 // 32 bf16 = 64B, padded to 80B
constexpr int MAT_BYTES  = 128 * LDS_ROW;    // 10240 per matrix per stage
constexpr int STAGE_BYTES = 4 * MAT_BYTES;   // Ah, Al, Bh, Bl
constexpr int STAGES   = 3;
constexpr int SMEM_NEED = STAGES * STAGE_BYTES;  // 122880

__device__ __forceinline__ void load_stage(
    uint32_t sbase, int kt, int K,
    const __nv_bfloat16* Ah_g, const __nv_bfloat16* Al_g,
    const __nv_bfloat16* Bh_g, const __nv_bfloat16* Bl_g, int tid)
{
    #pragma unroll
    for (int it = 0; it < 2; it++) {
        const int c  = tid + it * 256;        // 0..511
        const int r  = c >> 2;
        const int ch = c & 3;
        const uint32_t soff = (uint32_t)r * LDS_ROW + (uint32_t)ch * 16u;
        const size_t  goff = (size_t)r * K + kt + ch * 8;
        cp_async16(sbase + 0 * MAT_BYTES + soff, Ah_g + goff);
        cp_async16(sbase + 1 * MAT_BYTES + soff, Al_g + goff);
        cp_async16(sbase + 2 * MAT_BYTES + soff, Bh_g + goff);
        cp_async16(sbase + 3 * MAT_BYTES + soff, Bl_g + goff);
    }
}

template<bool HAS_BIAS, bool SPLIT>
__global__ void __launch_bounds__(256) mma_gemm_nt(
    const __nv_bfloat16* __restrict__ Ah, const __nv_bfloat16* __restrict__ Al,
    const __nv_bfloat16* __restrict__ Bh, const __nv_bfloat16* __restrict__ Bl,
    const float* __restrict__ bias,
    float* __restrict__ C, __nv_bfloat16* __restrict__ Ch, __nv_bfloat16* __restrict__ Cl,
    int M, int N, int K, float alpha,
    size_t sA, size_t sB, size_t sC)
{
    extern __shared__ char smem[];
    const uint32_t sb = smem_to_u32(smem);
    const int tid  = threadIdx.x;
    const int lane = tid & 31;
    const int wid  = tid >> 5;
    const int warp_m = wid & 3;       // 0..3
    const int warp_n = wid >> 2;      // 0..1

    const int row0 = blockIdx.y * 128;
    const int col0 = blockIdx.x * 128;
    const __nv_bfloat16* Ah_g = Ah + (size_t)blockIdx.z * sA + (size_t)row0 * K;
    const __nv_bfloat16* Al_g = Al + (size_t)blockIdx.z * sA + (size_t)row0 * K;
    const __nv_bfloat16* Bh_g = Bh + (size_t)blockIdx.z * sB + (size_t)col0 * K;
    const __nv_bfloat16* Bl_g = Bl + (size_t)blockIdx.z * sB + (size_t)col0 * K;

    const int nk = K / BK;

    // prologue: stages 0..STAGES-2
    #pragma unroll
    for (int s = 0; s < STAGES - 1; s++) {
        load_stage(sb + s * STAGE_BYTES, s * BK, K, Ah_g, Al_g, Bh_g, Bl_g, tid);
        cp_commit();
    }

    float d[2][8][4];
    #pragma unroll
    for (int mt = 0; mt < 2; mt++)
        #pragma unroll
        for (int nt = 0; nt < 8; nt++)
            #pragma unroll
            for (int e = 0; e < 4; e++) d[mt][nt][e] = 0.f;

    // fragment address components
    const uint32_t a_rowoff = (uint32_t)(warp_m * 32 + (lane & 15)) * LDS_ROW + ((lane >> 4) * 16);
    const uint32_t b_rowoff = (uint32_t)(warp_n * 64 + (lane & 7)) * LDS_ROW + (((lane >> 3) & 1) * 16);

    for (int ks = 0; ks < nk; ks++) {
        const int pre = ks + STAGES - 1;
        if (pre < nk)
            load_stage(sb + (pre % STAGES) * STAGE_BYTES, pre * BK, K, Ah_g, Al_g, Bh_g, Bl_g, tid);
        cp_commit();                  // always commit (empty groups keep the count)
        cp_wait<STAGES - 1>();        // stage ks resident
        __syncthreads();

        const uint32_t st = sb + (ks % STAGES) * STAGE_BYTES;
        #pragma unroll
        for (int kg = 0; kg < 2; kg++) {
            const uint32_t kb = kg * 32;
            uint32_t ah[2][4], al[2][4], bh[8][2], bl[8][2];
            #pragma unroll
            for (int mt = 0; mt < 2; mt++) {
                const uint32_t ao = a_rowoff + (uint32_t)mt * 16 * LDS_ROW + kb;
                ldsm_x4(ah[mt], st + 0 * MAT_BYTES + ao);
                ldsm_x4(al[mt], st + 1 * MAT_BYTES + ao);
            }
            #pragma unroll
            for (int nt = 0; nt < 8; nt++) {
                const uint32_t bo = b_rowoff + (uint32_t)nt * 8 * LDS_ROW + kb;
                ldsm_x2(bh[nt], st + 2 * MAT_BYTES + bo);
                ldsm_x2(bl[nt], st + 3 * MAT_BYTES + bo);
            }
            #pragma unroll
            for (int mt = 0; mt < 2; mt++)
                #pragma unroll
                for (int nt = 0; nt < 8; nt++) {
                    mma16816(d[mt][nt], ah[mt], bh[nt]);
                    mma16816(d[mt][nt], ah[mt], bl[nt]);
                    mma16816(d[mt][nt], al[mt], bh[nt]);
                }
        }
        __syncthreads();
    }

    // Epilogue
    const int lr  = lane >> 2;
    const int lc2 = (lane & 3) * 2;
    float* Cb = C + (size_t)blockIdx.z * sC;
    #pragma unroll
    for (int mt = 0; mt < 2; mt++) {
        #pragma unroll
        for (int part = 0; part < 2; part++) {
            const int row = row0 + warp_m * 32 + mt * 16 + lr + part * 8;
            const size_t rbase = (size_t)row * N;
            #pragma unroll
            for (int nt = 0; nt < 8; nt++) {
                const int col = col0 + warp_n * 64 + nt * 8 + lc2;
                float x0 = d[mt][nt][part * 2 + 0] * alpha;
                float x1 = d[mt][nt][part * 2 + 1] * alpha;
                if (HAS_BIAS) { x0 += bias[col]; x1 += bias[col + 1]; }
                *reinterpret_cast<float2*>(Cb + rbase + col) = make_float2(x0, x1);
                if (SPLIT) {
                    __nv_bfloat16 h0, l0, h1, l1;
                    split2(x0, h0, l0); split2(x1, h1, l1);
                    *reinterpret_cast<__nv_bfloat162*>(Ch + (size_t)blockIdx.z * sC + rbase + col) =
                        __halves2bfloat162(h0, h1);
                    *reinterpret_cast<__nv_bfloat162*>(Cl + (size_t)blockIdx.z * sC + rbase + col) =
                        __halves2bfloat162(l0, l1);
                }
            }
        }
    }
}

// ---------------------------------------------------------------------------
// fp32 -> (hi, lo) bf16 split, elementwise (4 elems / thread)
// ---------------------------------------------------------------------------
__global__ void __launch_bounds__(256) split_kernel(
    const float* __restrict__ x, __nv_bfloat16* __restrict__ h,
    __nv_bfloat16* __restrict__ l, size_t n)
{
    const size_t i = ((size_t)blockIdx.x * 256 + threadIdx.x) * 4;
    if (i >= n) return;
    float4 v = *reinterpret_cast<const float4*>(x + i);
    __nv_bfloat16 h0, l0, h1, l1, h2, l2, h3, l3;
    split2(v.x, h0, l0); split2(v.y, h1, l1);
    split2(v.z, h2, l2); split2(v.w, h3, l3);
    reinterpret_cast<__nv_bfloat162*>(h + i)[0] = __halves2bfloat162(h0, h1);
    reinterpret_cast<__nv_bfloat162*>(h + i)[1] = __halves2bfloat162(h2, h3);
    reinterpret_cast<__nv_bfloat162*>(l + i)[0] = __halves2bfloat162(l0, l1);
    reinterpret_cast<__nv_bfloat162*>(l + i)[1] = __halves2bfloat162(l2, l3);
}

// ---------------------------------------------------------------------------
// v [b][s][d] -> vT hi/lo [b][d][s]
// ---------------------------------------------------------------------------
__global__ void __launch_bounds__(256) transpose_split_kernel(
    const float* __restrict__ v, __nv_bfloat16* __restrict__ th,
    __nv_bfloat16* __restrict__ tl)
{
    __shared__ float tile[32][33];
    const int b = blockIdx.z;
    const int s0 = blockIdx.x * 32, d0 = blockIdx.y * 32;
    const float* vb = v + (size_t)b * SEQ * DIM;
    const int tx = threadIdx.x, ty = threadIdx.y;
    #pragma unroll
    for (int i = ty; i < 32; i += 8)
        tile[i][tx] = vb[(size_t)(s0 + i) * DIM + d0 + tx];
    __syncthreads();
    __nv_bfloat16* thb = th + (size_t)b * DIM * SEQ;
    __nv_bfloat16* tlb = tl + (size_t)b * DIM * SEQ;
    #pragma unroll
    for (int i = ty; i < 32; i += 8) {
        float x = tile[tx][i];
        __nv_bfloat16 h, l;
        split2(x, h, l);
        thb[(size_t)(d0 + i) * SEQ + s0 + tx] = h;
        tlb[(size_t)(d0 + i) * SEQ + s0 + tx] = l;
    }
}

// ---------------------------------------------------------------------------
// Block reductions (256 threads)
// ---------------------------------------------------------------------------
__device__ __forceinline__ float blk_red_sum(float v, float* sh) {
    #pragma unroll
    for (int o = 16; o > 0; o >>= 1) v += __shfl_xor_sync(0xffffffffu, v, o);
    __syncthreads();
    if ((threadIdx.x & 31) == 0) sh[threadIdx.x >> 5] = v;
    __syncthreads();
    float r = sh[0];
    #pragma unroll
    for (int w = 1; w < 8; w++) r += sh[w];
    return r;
}
__device__ __forceinline__ float blk_red_max(float v, float* sh) {
    #pragma unroll
    for (int o = 16; o > 0; o >>= 1) v = fmaxf(v, __shfl_xor_sync(0xffffffffu, v, o));
    __syncthreads();
    if ((threadIdx.x & 31) == 0) sh[threadIdx.x >> 5] = v;
    __syncthreads();
    float r = sh[0];
    #pragma unroll
    for (int w = 1; w < 8; w++) r = fmaxf(r, sh[w]);
    return r;
}

// ---------------------------------------------------------------------------
// Masked softmax over rows of scores [B,S,S]; outputs hi/lo split weights.
// ---------------------------------------------------------------------------
__global__ void __launch_bounds__(256) softmax_kernel(
    float* __restrict__ scores, const int* __restrict__ lengths,
    __nv_bfloat16* __restrict__ wh, __nv_bfloat16* __restrict__ wl)
{
    const int b = blockIdx.y;
    const int i = blockIdx.x;
    const int len = lengths[b];
    const size_t base = ((size_t)b * SEQ + i) * SEQ;
    float* row = scores + base;
    const int tid = threadIdx.x;
    __shared__ float sh[8];

    float m = -INFINITY;
    for (int j = tid; j < len; j += 256) m = fmaxf(m, row[j]);
    m = blk_red_max(m, sh);

    float s = 0.f;
    for (int j = tid; j < len; j += 256) {
        float e = __expf(row[j] - m);
        row[j] = e;
        s += e;
    }
    s = blk_red_sum(s, sh);
    const float inv = 1.f / s;

    for (int j = tid; j < SEQ; j += 256) {
        float w = (j < len) ? row[j] * inv : 0.f;
        __nv_bfloat16 h, l;
        split2(w, h, l);
        wh[base + j] = h;
        wl[base + j] = l;
    }
}

// ---------------------------------------------------------------------------
// out = LayerNorm( f(x1) + x2 ) * g + b, f = identity/ReLU; optional split out.
// ---------------------------------------------------------------------------
template<bool RELU, bool SPLIT>
__global__ void __launch_bounds__(256) add_ln_kernel(
    const float* __restrict__ x1, const float* __restrict__ x2,
    const float* __restrict__ g, const float* __restrict__ bvec,
    float* __restrict__ out, __nv_bfloat16* __restrict__ oh,
    __nv_bfloat16* __restrict__ ol)
{
    const size_t row = blockIdx.x;
    const int tid = threadIdx.x;
    __shared__ float sh[8];

    float4 a = reinterpret_cast<const float4*>(x1 + row * DIM)[tid];
    float4 c = reinterpret_cast<const float4*>(x2 + row * DIM)[tid];
    if (RELU) {
        a.x = fmaxf(a.x, 0.f); a.y = fmaxf(a.y, 0.f);
        a.z = fmaxf(a.z, 0.f); a.w = fmaxf(a.w, 0.f);
    }
    float x0 = a.x + c.x, x1v = a.y + c.y, x2v = a.z + c.z, x3 = a.w + c.w;

    float s = x0 + x1v + x2v + x3;
    s = blk_red_sum(s, sh);
    const float mean = s * (1.f / DIM);

    float d0 = x0 - mean, d1 = x1v - mean, d2 = x2v - mean, d3 = x3 - mean;
    float sq = d0 * d0 + d1 * d1 + d2 * d2 + d3 * d3;
    sq = blk_red_sum(sq, sh);
    const float rstd = rsqrtf(sq * (1.f / DIM) + EPS);

    float4 gv = reinterpret_cast<const float4*>(g)[tid];
    float4 bv = reinterpret_cast<const float4*>(bvec)[tid];
    float4 o;
    o.x = d0 * rstd * gv.x + bv.x;
    o.y = d1 * rstd * gv.y + bv.y;
    o.z = d2 * rstd * gv.z + bv.z;
    o.w = d3 * rstd * gv.w + bv.w;
    reinterpret_cast<float4*>(out + row * DIM)[tid] = o;

    if (SPLIT) {
        __nv_bfloat16 h0, l0, h1, l1, h2, l2, h3, l3;
        split2(o.x, h0, l0); split2(o.y, h1, l1);
        split2(o.z, h2, l2); split2(o.w, h3, l3);
        const size_t i = row * DIM + (size_t)tid * 4;
        reinterpret_cast<__nv_bfloat162*>(oh + i)[0] = __halves2bfloat162(h0, h1);
        reinterpret_cast<__nv_bfloat162*>(oh + i)[1] = __halves2bfloat162(h2, h3);
        reinterpret_cast<__nv_bfloat162*>(ol + i)[0] = __halves2bfloat162(l0, l1);
        reinterpret_cast<__nv_bfloat162*>(ol + i)[1] = __halves2bfloat162(l2, l3);
    }
}

// ---------------------------------------------------------------------------
// Launch
// ---------------------------------------------------------------------------
extern "C" void kernel_launch(void* const* d_in, const int* in_sizes, int n_in,
                              void* d_out, int out_size)
{
    const float* seq     = (const float*)d_in[0];
    const int*   lengths = (const int*)  d_in[1];
    const float* Wq = (const float*)d_in[2];  const float* bq = (const float*)d_in[3];
    const float* Wk = (const float*)d_in[4];  const float* bk = (const float*)d_in[5];
    const float* Wv = (const float*)d_in[6];  const float* bv = (const float*)d_in[7];
    const float* Wo = (const float*)d_in[8];  const float* bo = (const float*)d_in[9];
    const float* g1 = (const float*)d_in[10]; const float* b1 = (const float*)d_in[11];
    const float* g2 = (const float*)d_in[12]; const float* b2 = (const float*)d_in[13];
    float* out = (float*)d_out;

    float *q, *v, *sc, *attn, *post, *h;
    cudaGetSymbolAddress((void**)&q,    g_q);
    cudaGetSymbolAddress((void**)&v,    g_v);
    cudaGetSymbolAddress((void**)&sc,   g_sc);
    cudaGetSymbolAddress((void**)&attn, g_attn);
    cudaGetSymbolAddress((void**)&post, g_post);
    cudaGetSymbolAddress((void**)&h,    g_h);

    __nv_bfloat16 *seqh, *seql, *Wqh, *Wql, *Wkh, *Wkl, *Wvh, *Wvl, *Woh, *Wol;
    __nv_bfloat16 *qh, *ql, *kh, *kl, *vTh, *vTl, *sch, *scl, *posth, *postl;
    cudaGetSymbolAddress((void**)&seqh, g_seq_h); cudaGetSymbolAddress((void**)&seql, g_seq_l);
    cudaGetSymbolAddress((void**)&Wqh,  g_Wq_h);  cudaGetSymbolAddress((void**)&Wql,  g_Wq_l);
    cudaGetSymbolAddress((void**)&Wkh,  g_Wk_h);  cudaGetSymbolAddress((void**)&Wkl,  g_Wk_l);
    cudaGetSymbolAddress((void**)&Wvh,  g_Wv_h);  cudaGetSymbolAddress((void**)&Wvl,  g_Wv_l);
    cudaGetSymbolAddress((void**)&Woh,  g_Wo_h);  cudaGetSymbolAddress((void**)&Wol,  g_Wo_l);
    cudaGetSymbolAddress((void**)&qh,   g_q_h);   cudaGetSymbolAddress((void**)&ql,   g_q_l);
    cudaGetSymbolAddress((void**)&kh,   g_k_h);   cudaGetSymbolAddress((void**)&kl,   g_k_l);
    cudaGetSymbolAddress((void**)&vTh,  g_vT_h);  cudaGetSymbolAddress((void**)&vTl,  g_vT_l);
    cudaGetSymbolAddress((void**)&sch,  g_sc_h);  cudaGetSymbolAddress((void**)&scl,  g_sc_l);
    cudaGetSymbolAddress((void**)&posth, g_post_h); cudaGetSymbolAddress((void**)&postl, g_post_l);

    cudaFuncSetAttribute(mma_gemm_nt<true,  true >, cudaFuncAttributeMaxDynamicSharedMemorySize, SMEM_NEED);
    cudaFuncSetAttribute(mma_gemm_nt<true,  false>, cudaFuncAttributeMaxDynamicSharedMemorySize, SMEM_NEED);
    cudaFuncSetAttribute(mma_gemm_nt<false, false>, cudaFuncAttributeMaxDynamicSharedMemorySize, SMEM_NEED);
    cudaFuncSetAttribute(mma_gemm_nt<false, true >, cudaFuncAttributeMaxDynamicSharedMemorySize, SMEM_NEED);

    const int M = BATCH * SEQ;                 // 16384
    const size_t sBD = (size_t)SEQ * DIM;
    const size_t sDS = (size_t)DIM * SEQ;
    const size_t sSS = (size_t)SEQ * SEQ;

    // 0) split conversions
    const size_t nseq = (size_t)M * DIM;
    split_kernel<<<(unsigned)(nseq / 1024), 256>>>(seq, seqh, seql, nseq);
    const size_t nw = (size_t)DIM * DIM;
    split_kernel<<<(unsigned)(nw / 1024), 256>>>(Wq, Wqh, Wql, nw);
    split_kernel<<<(unsigned)(nw / 1024), 256>>>(Wk, Wkh, Wkl, nw);
    split_kernel<<<(unsigned)(nw / 1024), 256>>>(Wv, Wvh, Wvl, nw);
    split_kernel<<<(unsigned)(nw / 1024), 256>>>(Wo, Woh, Wol, nw);

    dim3 blk(256);
    // 1) projections: [16384,1024] = seq @ W^T + b  (q,k produce split outputs)
    dim3 gproj(DIM / 128, M / 128, 1);
    mma_gemm_nt<true, true ><<<gproj, blk, SMEM_NEED>>>(seqh, seql, Wqh, Wql, bq, q, qh, ql, M, DIM, DIM, 1.f, 0, 0, 0);
    mma_gemm_nt<true, true ><<<gproj, blk, SMEM_NEED>>>(seqh, seql, Wkh, Wkl, bk, q, kh, kl, M, DIM, DIM, 1.f, 0, 0, 0);
    mma_gemm_nt<true, false><<<gproj, blk, SMEM_NEED>>>(seqh, seql, Wvh, Wvl, bv, v, nullptr, nullptr, M, DIM, DIM, 1.f, 0, 0, 0);

    // 2) v -> vT hi/lo
    dim3 gtr(SEQ / 32, DIM / 32, BATCH);
    transpose_split_kernel<<<gtr, dim3(32, 8)>>>(v, vTh, vTl);

    // 3) scores = q @ k^T / 32, per batch
    dim3 gsc(SEQ / 128, SEQ / 128, BATCH);
    mma_gemm_nt<false, false><<<gsc, blk, SMEM_NEED>>>(qh, ql, kh, kl, nullptr, sc, nullptr, nullptr,
                                                       SEQ, SEQ, DIM, 1.f / 32.f, sBD, sBD, sSS);

    // 4) masked softmax -> split weights
    dim3 gsm(SEQ, BATCH);
    softmax_kernel<<<gsm, 256>>>(sc, lengths, sch, scl);

    // 5) attn = w @ vT^T, per batch (K = SEQ)
    dim3 gav(DIM / 128, SEQ / 128, BATCH);
    mma_gemm_nt<false, false><<<gav, blk, SMEM_NEED>>>(sch, scl, vTh, vTl, nullptr, attn, nullptr, nullptr,
                                                       SEQ, DIM, SEQ, 1.f, sSS, sDS, sBD);

    // 6) post = LN(attn + seq), with split
    add_ln_kernel<false, true><<<M, 256>>>(attn, seq, g1, b1, post, posth, postl);

    // 7) h = post @ Wo^T + bo
    mma_gemm_nt<true, false><<<gproj, blk, SMEM_NEED>>>(posth, postl, Woh, Wol, bo, h, nullptr, nullptr,
                                                        M, DIM, DIM, 1.f, 0, 0, 0);

    // 8) out = LN(relu(h) + post)
    add_ln_kernel<true, false><<<M, 256>>>(h, post, g2, b2, out, nullptr, nullptr);
}

// round 4
// speedup vs baseline: 2.5129x; 1.1617x over previous
#include <cuda_runtime.h>
#include <cuda_bf16.h>
#include <math.h>
#include <stdint.h>

// Problem constants
constexpr int BATCH = 8;
constexpr int SEQ   = 2048;
constexpr int DIM   = 1024;
constexpr float EPS = 1e-5f;

// ---------------------------------------------------------------------------
// Scratch (device globals — no allocations allowed)
// ---------------------------------------------------------------------------
__device__ __align__(256) float g_v   [(size_t)BATCH * SEQ * DIM];
__device__ __align__(256) float g_sc  [(size_t)BATCH * SEQ * SEQ];
__device__ __align__(256) float g_attn[(size_t)BATCH * SEQ * DIM];
__device__ __align__(256) float g_post[(size_t)BATCH * SEQ * DIM];
__device__ __align__(256) float g_h   [(size_t)BATCH * SEQ * DIM];

// split (hi/lo bf16) operand buffers
__device__ __align__(256) __nv_bfloat16 g_seq_h[(size_t)BATCH*SEQ*DIM], g_seq_l[(size_t)BATCH*SEQ*DIM];
__device__ __align__(256) __nv_bfloat16 g_Wq_h[(size_t)DIM*DIM], g_Wq_l[(size_t)DIM*DIM];
__device__ __align__(256) __nv_bfloat16 g_Wk_h[(size_t)DIM*DIM], g_Wk_l[(size_t)DIM*DIM];
__device__ __align__(256) __nv_bfloat16 g_Wv_h[(size_t)DIM*DIM], g_Wv_l[(size_t)DIM*DIM];
__device__ __align__(256) __nv_bfloat16 g_Wo_h[(size_t)DIM*DIM], g_Wo_l[(size_t)DIM*DIM];
__device__ __align__(256) __nv_bfloat16 g_q_h [(size_t)BATCH*SEQ*DIM], g_q_l [(size_t)BATCH*SEQ*DIM];
__device__ __align__(256) __nv_bfloat16 g_k_h [(size_t)BATCH*SEQ*DIM], g_k_l [(size_t)BATCH*SEQ*DIM];
__device__ __align__(256) __nv_bfloat16 g_vT_h[(size_t)BATCH*DIM*SEQ], g_vT_l[(size_t)BATCH*DIM*SEQ];
__device__ __align__(256) __nv_bfloat16 g_sc_h[(size_t)BATCH*SEQ*SEQ], g_sc_l[(size_t)BATCH*SEQ*SEQ];
__device__ __align__(256) __nv_bfloat16 g_post_h[(size_t)BATCH*SEQ*DIM], g_post_l[(size_t)BATCH*SEQ*DIM];

// ---------------------------------------------------------------------------
// PTX helpers (compute_80-safe: cp.async, ldmatrix, mma.sync)
// ---------------------------------------------------------------------------
__device__ __forceinline__ uint32_t smem_to_u32(const void* p) {
    uint32_t a;
    asm("{ .reg .u64 t; cvta.to.shared.u64 t, %1; cvt.u32.u64 %0, t; }" : "=r"(a) : "l"(p));
    return a;
}
__device__ __forceinline__ void cp_async16(uint32_t s, const void* g) {
    asm volatile("cp.async.cg.shared.global [%0], [%1], 16;" :: "r"(s), "l"(g));
}
__device__ __forceinline__ void cp_commit() { asm volatile("cp.async.commit_group;" ::: "memory"); }
template<int N> __device__ __forceinline__ void cp_wait() {
    asm volatile("cp.async.wait_group %0;" :: "n"(N) : "memory");
}
__device__ __forceinline__ void ldsm_x4(uint32_t* r, uint32_t a) {
    asm volatile("ldmatrix.sync.aligned.m8n8.x4.shared.b16 {%0,%1,%2,%3}, [%4];"
                 : "=r"(r[0]), "=r"(r[1]), "=r"(r[2]), "=r"(r[3]) : "r"(a));
}
__device__ __forceinline__ void ldsm_x2(uint32_t* r, uint32_t a) {
    asm volatile("ldmatrix.sync.aligned.m8n8.x2.shared.b16 {%0,%1}, [%2];"
                 : "=r"(r[0]), "=r"(r[1]) : "r"(a));
}
__device__ __forceinline__ void mma16816(float* d, const uint32_t* a, const uint32_t* b) {
    asm volatile(
        "mma.sync.aligned.m16n8k16.row.col.f32.bf16.bf16.f32 "
        "{%0,%1,%2,%3}, {%4,%5,%6,%7}, {%8,%9}, {%0,%1,%2,%3};"
        : "+f"(d[0]), "+f"(d[1]), "+f"(d[2]), "+f"(d[3])
        : "r"(a[0]), "r"(a[1]), "r"(a[2]), "r"(a[3]), "r"(b[0]), "r"(b[1]));
}

__device__ __forceinline__ void split2(float x, __nv_bfloat16& h, __nv_bfloat16& l) {
    h = __float2bfloat16_rn(x);
    l = __float2bfloat16_rn(x - __bfloat162float(h));
}

// ---------------------------------------------------------------------------
// HMMA GEMM NT: C = alpha * A @ B^T (+ bias). A:[M,K] hi/lo bf16, B:[N,K] hi/lo.
// Block 256x128, 8 warps (4m x 2n), warp tile 64x64, BK=32, 3-stage cp.async,
// single __syncthreads per stage (wait -> sync -> prefetch ks+2 -> compute).
// ---------------------------------------------------------------------------
constexpr int BM = 256, BN = 128, BK = 32;
constexpr int LDS_ROW     = 80;                 // 64B data + 16B pad
constexpr int A_BYTES     = BM * LDS_ROW;       // 20480
constexpr int B_BYTES     = BN * LDS_ROW;       // 10240
constexpr int STAGE_BYTES = 2 * A_BYTES + 2 * B_BYTES;  // 61440
constexpr int STAGES      = 3;
constexpr int SMEM_NEED   = STAGES * STAGE_BYTES;       // 184320

__device__ __forceinline__ void load_stage(
    uint32_t sbase, int kt, int K,
    const __nv_bfloat16* Ah_g, const __nv_bfloat16* Al_g,
    const __nv_bfloat16* Bh_g, const __nv_bfloat16* Bl_g, int tid)
{
    #pragma unroll
    for (int it = 0; it < 4; it++) {                 // A: 256 rows x 4 chunks
        const int c  = tid + it * 256;
        const int r  = c >> 2, ch = c & 3;
        const uint32_t soff = (uint32_t)r * LDS_ROW + (uint32_t)ch * 16u;
        const size_t  goff = (size_t)r * K + kt + ch * 8;
        cp_async16(sbase + soff,            Ah_g + goff);
        cp_async16(sbase + A_BYTES + soff,  Al_g + goff);
    }
    #pragma unroll
    for (int it = 0; it < 2; it++) {                 // B: 128 rows x 4 chunks
        const int c  = tid + it * 256;
        const int r  = c >> 2, ch = c & 3;
        const uint32_t soff = (uint32_t)r * LDS_ROW + (uint32_t)ch * 16u;
        const size_t  goff = (size_t)r * K + kt + ch * 8;
        cp_async16(sbase + 2 * A_BYTES + soff,           Bh_g + goff);
        cp_async16(sbase + 2 * A_BYTES + B_BYTES + soff, Bl_g + goff);
    }
    cp_commit();
}

template<bool HAS_BIAS, bool SPLIT, bool WRITE_F32, bool LEN_EXIT, bool LEN_TRUNC>
__global__ void __launch_bounds__(256) mma_gemm_nt(
    const __nv_bfloat16* __restrict__ Ah, const __nv_bfloat16* __restrict__ Al,
    const __nv_bfloat16* __restrict__ Bh, const __nv_bfloat16* __restrict__ Bl,
    const float* __restrict__ bias, const int* __restrict__ lengths,
    float* __restrict__ C, __nv_bfloat16* __restrict__ Ch, __nv_bfloat16* __restrict__ Cl,
    int M, int N, int K, float alpha,
    size_t sA, size_t sB, size_t sC)
{
    const int col0 = blockIdx.x * BN;
    int len = 0;
    if (LEN_EXIT || LEN_TRUNC) {
        len = lengths[blockIdx.z];
        if (LEN_EXIT && col0 >= len) return;   // masked-out score columns: skip
    }

    extern __shared__ char smem[];
    const uint32_t sb = smem_to_u32(smem);
    const int tid  = threadIdx.x;
    const int lane = tid & 31;
    const int wid  = tid >> 5;
    const int warp_m = wid & 3;       // 0..3 -> 64 rows each
    const int warp_n = wid >> 2;      // 0..1 -> 64 cols each

    const int row0 = blockIdx.y * BM;
    const __nv_bfloat16* Ah_g = Ah + (size_t)blockIdx.z * sA + (size_t)row0 * K;
    const __nv_bfloat16* Al_g = Al + (size_t)blockIdx.z * sA + (size_t)row0 * K;
    const __nv_bfloat16* Bh_g = Bh + (size_t)blockIdx.z * sB + (size_t)col0 * K;
    const __nv_bfloat16* Bl_g = Bl + (size_t)blockIdx.z * sB + (size_t)col0 * K;

    int nk = K / BK;
    if (LEN_TRUNC) nk = (len + BK - 1) / BK;   // weights beyond len are exact zeros

    // prologue: stages 0, 1
    load_stage(sb,               0,  K, Ah_g, Al_g, Bh_g, Bl_g, tid);
    load_stage(sb + STAGE_BYTES, BK, K, Ah_g, Al_g, Bh_g, Bl_g, tid);

    float d[4][8][4];
    #pragma unroll
    for (int mt = 0; mt < 4; mt++)
        #pragma unroll
        for (int nt = 0; nt < 8; nt++)
            #pragma unroll
            for (int e = 0; e < 4; e++) d[mt][nt][e] = 0.f;

    const uint32_t a_base = (uint32_t)(warp_m * 64 + (lane & 15)) * LDS_ROW + ((lane >> 4) * 16);
    const uint32_t b_base = (uint32_t)(warp_n * 64 + (lane & 7)) * LDS_ROW + (((lane >> 3) & 1) * 16);

    int sidx = 0;                      // ks % 3
    for (int ks = 0; ks < nk; ks++) {
        if (ks + 1 < nk) cp_wait<1>(); else cp_wait<0>();
        __syncthreads();

        const int pre = ks + 2;
        if (pre < nk) {
            int pidx = sidx + 2; if (pidx >= 3) pidx -= 3;
            load_stage(sb + pidx * STAGE_BYTES, pre * BK, K, Ah_g, Al_g, Bh_g, Bl_g, tid);
        }

        const uint32_t st = sb + sidx * STAGE_BYTES;
        #pragma unroll
        for (int kg = 0; kg < 2; kg++) {
            const uint32_t kb = kg * 32;
            uint32_t ah[4][4], al[4][4];
            #pragma unroll
            for (int mt = 0; mt < 4; mt++) {
                const uint32_t ao = a_base + (uint32_t)mt * 16 * LDS_ROW + kb;
                ldsm_x4(ah[mt], st + ao);
                ldsm_x4(al[mt], st + A_BYTES + ao);
            }
            #pragma unroll
            for (int nh = 0; nh < 2; nh++) {
                uint32_t bh[4][2], bl[4][2];
                #pragma unroll
                for (int nt = 0; nt < 4; nt++) {
                    const uint32_t bo = b_base + (uint32_t)(nh * 4 + nt) * 8 * LDS_ROW + kb;
                    ldsm_x2(bh[nt], st + 2 * A_BYTES + bo);
                    ldsm_x2(bl[nt], st + 2 * A_BYTES + B_BYTES + bo);
                }
                #pragma unroll
                for (int mt = 0; mt < 4; mt++)
                    #pragma unroll
                    for (int nt = 0; nt < 4; nt++) {
                        float* dd = d[mt][nh * 4 + nt];
                        mma16816(dd, ah[mt], bh[nt]);
                        mma16816(dd, ah[mt], bl[nt]);
                        mma16816(dd, al[mt], bh[nt]);
                    }
            }
        }
        if (++sidx == 3) sidx = 0;
    }

    // Epilogue
    const int lr  = lane >> 2;
    const int lc2 = (lane & 3) * 2;
    const size_t zoff = (size_t)blockIdx.z * sC;
    #pragma unroll
    for (int mt = 0; mt < 4; mt++) {
        #pragma unroll
        for (int part = 0; part < 2; part++) {
            const int row = row0 + warp_m * 64 + mt * 16 + part * 8 + lr;
            const size_t rbase = zoff + (size_t)row * N;
            #pragma unroll
            for (int nt = 0; nt < 8; nt++) {
                const int col = col0 + warp_n * 64 + nt * 8 + lc2;
                float x0 = d[mt][nt][part * 2 + 0] * alpha;
                float x1 = d[mt][nt][part * 2 + 1] * alpha;
                if (HAS_BIAS) { x0 += bias[col]; x1 += bias[col + 1]; }
                if (WRITE_F32)
                    *reinterpret_cast<float2*>(C + rbase + col) = make_float2(x0, x1);
                if (SPLIT) {
                    __nv_bfloat16 h0, l0, h1, l1;
                    split2(x0, h0, l0); split2(x1, h1, l1);
                    *reinterpret_cast<__nv_bfloat162*>(Ch + rbase + col) = __halves2bfloat162(h0, h1);
                    *reinterpret_cast<__nv_bfloat162*>(Cl + rbase + col) = __halves2bfloat162(l0, l1);
                }
            }
        }
    }
}

// ---------------------------------------------------------------------------
// fp32 -> (hi, lo) bf16 split, elementwise (4 elems / thread)
// ---------------------------------------------------------------------------
__global__ void __launch_bounds__(256) split_kernel(
    const float* __restrict__ x, __nv_bfloat16* __restrict__ h,
    __nv_bfloat16* __restrict__ l, size_t n)
{
    const size_t i = ((size_t)blockIdx.x * 256 + threadIdx.x) * 4;
    if (i >= n) return;
    float4 v = *reinterpret_cast<const float4*>(x + i);
    __nv_bfloat16 h0, l0, h1, l1, h2, l2, h3, l3;
    split2(v.x, h0, l0); split2(v.y, h1, l1);
    split2(v.z, h2, l2); split2(v.w, h3, l3);
    reinterpret_cast<__nv_bfloat162*>(h + i)[0] = __halves2bfloat162(h0, h1);
    reinterpret_cast<__nv_bfloat162*>(h + i)[1] = __halves2bfloat162(h2, h3);
    reinterpret_cast<__nv_bfloat162*>(l + i)[0] = __halves2bfloat162(l0, l1);
    reinterpret_cast<__nv_bfloat162*>(l + i)[1] = __halves2bfloat162(l2, l3);
}

// ---------------------------------------------------------------------------
// v [b][s][d] -> vT hi/lo [b][d][s]
// ---------------------------------------------------------------------------
__global__ void __launch_bounds__(256) transpose_split_kernel(
    const float* __restrict__ v, __nv_bfloat16* __restrict__ th,
    __nv_bfloat16* __restrict__ tl)
{
    __shared__ float tile[32][33];
    const int b = blockIdx.z;
    const int s0 = blockIdx.x * 32, d0 = blockIdx.y * 32;
    const float* vb = v + (size_t)b * SEQ * DIM;
    const int tx = threadIdx.x, ty = threadIdx.y;
    #pragma unroll
    for (int i = ty; i < 32; i += 8)
        tile[i][tx] = vb[(size_t)(s0 + i) * DIM + d0 + tx];
    __syncthreads();
    __nv_bfloat16* thb = th + (size_t)b * DIM * SEQ;
    __nv_bfloat16* tlb = tl + (size_t)b * DIM * SEQ;
    #pragma unroll
    for (int i = ty; i < 32; i += 8) {
        float x = tile[tx][i];
        __nv_bfloat16 h, l;
        split2(x, h, l);
        thb[(size_t)(d0 + i) * SEQ + s0 + tx] = h;
        tlb[(size_t)(d0 + i) * SEQ + s0 + tx] = l;
    }
}

// ---------------------------------------------------------------------------
// Block reductions (256 threads)
// ---------------------------------------------------------------------------
__device__ __forceinline__ float blk_red_sum(float v, float* sh) {
    #pragma unroll
    for (int o = 16; o > 0; o >>= 1) v += __shfl_xor_sync(0xffffffffu, v, o);
    __syncthreads();
    if ((threadIdx.x & 31) == 0) sh[threadIdx.x >> 5] = v;
    __syncthreads();
    float r = sh[0];
    #pragma unroll
    for (int w = 1; w < 8; w++) r += sh[w];
    return r;
}
__device__ __forceinline__ float blk_red_max(float v, float* sh) {
    #pragma unroll
    for (int o = 16; o > 0; o >>= 1) v = fmaxf(v, __shfl_xor_sync(0xffffffffu, v, o));
    __syncthreads();
    if ((threadIdx.x & 31) == 0) sh[threadIdx.x >> 5] = v;
    __syncthreads();
    float r = sh[0];
    #pragma unroll
    for (int w = 1; w < 8; w++) r = fmaxf(r, sh[w]);
    return r;
}

// ---------------------------------------------------------------------------
// Masked softmax over rows of scores [B,S,S]; outputs hi/lo split weights.
// ---------------------------------------------------------------------------
__global__ void __launch_bounds__(256) softmax_kernel(
    float* __restrict__ scores, const int* __restrict__ lengths,
    __nv_bfloat16* __restrict__ wh, __nv_bfloat16* __restrict__ wl)
{
    const int b = blockIdx.y;
    const int i = blockIdx.x;
    const int len = lengths[b];
    const size_t base = ((size_t)b * SEQ + i) * SEQ;
    float* row = scores + base;
    const int tid = threadIdx.x;
    __shared__ float sh[8];

    float m = -INFINITY;
    for (int j = tid; j < len; j += 256) m = fmaxf(m, row[j]);
    m = blk_red_max(m, sh);

    float s = 0.f;
    for (int j = tid; j < len; j += 256) {
        float e = __expf(row[j] - m);
        row[j] = e;
        s += e;
    }
    s = blk_red_sum(s, sh);
    const float inv = 1.f / s;

    for (int j = tid; j < SEQ; j += 256) {
        float w = (j < len) ? row[j] * inv : 0.f;
        __nv_bfloat16 h, l;
        split2(w, h, l);
        wh[base + j] = h;
        wl[base + j] = l;
    }
}

// ---------------------------------------------------------------------------
// out = LayerNorm( f(x1) + x2 ) * g + b, f = identity/ReLU; optional split out.
// ---------------------------------------------------------------------------
template<bool RELU, bool SPLIT>
__global__ void __launch_bounds__(256) add_ln_kernel(
    const float* __restrict__ x1, const float* __restrict__ x2,
    const float* __restrict__ g, const float* __restrict__ bvec,
    float* __restrict__ out, __nv_bfloat16* __restrict__ oh,
    __nv_bfloat16* __restrict__ ol)
{
    const size_t row = blockIdx.x;
    const int tid = threadIdx.x;
    __shared__ float sh[8];

    float4 a = reinterpret_cast<const float4*>(x1 + row * DIM)[tid];
    float4 c = reinterpret_cast<const float4*>(x2 + row * DIM)[tid];
    if (RELU) {
        a.x = fmaxf(a.x, 0.f); a.y = fmaxf(a.y, 0.f);
        a.z = fmaxf(a.z, 0.f); a.w = fmaxf(a.w, 0.f);
    }
    float x0 = a.x + c.x, x1v = a.y + c.y, x2v = a.z + c.z, x3 = a.w + c.w;

    float s = x0 + x1v + x2v + x3;
    s = blk_red_sum(s, sh);
    const float mean = s * (1.f / DIM);

    float d0 = x0 - mean, d1 = x1v - mean, d2 = x2v - mean, d3 = x3 - mean;
    float sq = d0 * d0 + d1 * d1 + d2 * d2 + d3 * d3;
    sq = blk_red_sum(sq, sh);
    const float rstd = rsqrtf(sq * (1.f / DIM) + EPS);

    float4 gv = reinterpret_cast<const float4*>(g)[tid];
    float4 bv = reinterpret_cast<const float4*>(bvec)[tid];
    float4 o;
    o.x = d0 * rstd * gv.x + bv.x;
    o.y = d1 * rstd * gv.y + bv.y;
    o.z = d2 * rstd * gv.z + bv.z;
    o.w = d3 * rstd * gv.w + bv.w;
    reinterpret_cast<float4*>(out + row * DIM)[tid] = o;

    if (SPLIT) {
        __nv_bfloat16 h0, l0, h1, l1, h2, l2, h3, l3;
        split2(o.x, h0, l0); split2(o.y, h1, l1);
        split2(o.z, h2, l2); split2(o.w, h3, l3);
        const size_t i = row * DIM + (size_t)tid * 4;
        reinterpret_cast<__nv_bfloat162*>(oh + i)[0] = __halves2bfloat162(h0, h1);
        reinterpret_cast<__nv_bfloat162*>(oh + i)[1] = __halves2bfloat162(h2, h3);
        reinterpret_cast<__nv_bfloat162*>(ol + i)[0] = __halves2bfloat162(l0, l1);
        reinterpret_cast<__nv_bfloat162*>(ol + i)[1] = __halves2bfloat162(l2, l3);
    }
}

// ---------------------------------------------------------------------------
// Launch
// ---------------------------------------------------------------------------
extern "C" void kernel_launch(void* const* d_in, const int* in_sizes, int n_in,
                              void* d_out, int out_size)
{
    const float* seq     = (const float*)d_in[0];
    const int*   lengths = (const int*)  d_in[1];
    const float* Wq = (const float*)d_in[2];  const float* bq = (const float*)d_in[3];
    const float* Wk = (const float*)d_in[4];  const float* bk = (const float*)d_in[5];
    const float* Wv = (const float*)d_in[6];  const float* bv = (const float*)d_in[7];
    const float* Wo = (const float*)d_in[8];  const float* bo = (const float*)d_in[9];
    const float* g1 = (const float*)d_in[10]; const float* b1 = (const float*)d_in[11];
    const float* g2 = (const float*)d_in[12]; const float* b2 = (const float*)d_in[13];
    float* out = (float*)d_out;

    float *v, *sc, *attn, *post, *h;
    cudaGetSymbolAddress((void**)&v,    g_v);
    cudaGetSymbolAddress((void**)&sc,   g_sc);
    cudaGetSymbolAddress((void**)&attn, g_attn);
    cudaGetSymbolAddress((void**)&post, g_post);
    cudaGetSymbolAddress((void**)&h,    g_h);

    __nv_bfloat16 *seqh, *seql, *Wqh, *Wql, *Wkh, *Wkl, *Wvh, *Wvl, *Woh, *Wol;
    __nv_bfloat16 *qh, *ql, *kh, *kl, *vTh, *vTl, *sch, *scl, *posth, *postl;
    cudaGetSymbolAddress((void**)&seqh, g_seq_h); cudaGetSymbolAddress((void**)&seql, g_seq_l);
    cudaGetSymbolAddress((void**)&Wqh,  g_Wq_h);  cudaGetSymbolAddress((void**)&Wql,  g_Wq_l);
    cudaGetSymbolAddress((void**)&Wkh,  g_Wk_h);  cudaGetSymbolAddress((void**)&Wkl,  g_Wk_l);
    cudaGetSymbolAddress((void**)&Wvh,  g_Wv_h);  cudaGetSymbolAddress((void**)&Wvl,  g_Wv_l);
    cudaGetSymbolAddress((void**)&Woh,  g_Wo_h);  cudaGetSymbolAddress((void**)&Wol,  g_Wo_l);
    cudaGetSymbolAddress((void**)&qh,   g_q_h);   cudaGetSymbolAddress((void**)&ql,   g_q_l);
    cudaGetSymbolAddress((void**)&kh,   g_k_h);   cudaGetSymbolAddress((void**)&kl,   g_k_l);
    cudaGetSymbolAddress((void**)&vTh,  g_vT_h);  cudaGetSymbolAddress((void**)&vTl,  g_vT_l);
    cudaGetSymbolAddress((void**)&sch,  g_sc_h);  cudaGetSymbolAddress((void**)&scl,  g_sc_l);
    cudaGetSymbolAddress((void**)&posth, g_post_h); cudaGetSymbolAddress((void**)&postl, g_post_l);

    cudaFuncSetAttribute(mma_gemm_nt<true,  true,  false, false, false>, cudaFuncAttributeMaxDynamicSharedMemorySize, SMEM_NEED);
    cudaFuncSetAttribute(mma_gemm_nt<true,  false, true,  false, false>, cudaFuncAttributeMaxDynamicSharedMemorySize, SMEM_NEED);
    cudaFuncSetAttribute(mma_gemm_nt<false, false, true,  true,  false>, cudaFuncAttributeMaxDynamicSharedMemorySize, SMEM_NEED);
    cudaFuncSetAttribute(mma_gemm_nt<false, false, true,  false, true >, cudaFuncAttributeMaxDynamicSharedMemorySize, SMEM_NEED);

    const int M = BATCH * SEQ;                 // 16384
    const size_t sBD = (size_t)SEQ * DIM;
    const size_t sDS = (size_t)DIM * SEQ;
    const size_t sSS = (size_t)SEQ * SEQ;

    // 0) split conversions
    const size_t nseq = (size_t)M * DIM;
    split_kernel<<<(unsigned)(nseq / 1024), 256>>>(seq, seqh, seql, nseq);
    const size_t nw = (size_t)DIM * DIM;
    split_kernel<<<(unsigned)(nw / 1024), 256>>>(Wq, Wqh, Wql, nw);
    split_kernel<<<(unsigned)(nw / 1024), 256>>>(Wk, Wkh, Wkl, nw);
    split_kernel<<<(unsigned)(nw / 1024), 256>>>(Wv, Wvh, Wvl, nw);
    split_kernel<<<(unsigned)(nw / 1024), 256>>>(Wo, Woh, Wol, nw);

    dim3 blk(256);
    // 1) projections: [16384,1024] = seq @ W^T + b (q,k split-only; v fp32-only)
    dim3 gproj(DIM / BN, M / BM, 1);
    mma_gemm_nt<true, true, false, false, false><<<gproj, blk, SMEM_NEED>>>(
        seqh, seql, Wqh, Wql, bq, nullptr, nullptr, qh, ql, M, DIM, DIM, 1.f, 0, 0, 0);
    mma_gemm_nt<true, true, false, false, false><<<gproj, blk, SMEM_NEED>>>(
        seqh, seql, Wkh, Wkl, bk, nullptr, nullptr, kh, kl, M, DIM, DIM, 1.f, 0, 0, 0);
    mma_gemm_nt<true, false, true, false, false><<<gproj, blk, SMEM_NEED>>>(
        seqh, seql, Wvh, Wvl, bv, nullptr, v, nullptr, nullptr, M, DIM, DIM, 1.f, 0, 0, 0);

    // 2) v -> vT hi/lo
    dim3 gtr(SEQ / 32, DIM / 32, BATCH);
    transpose_split_kernel<<<gtr, dim3(32, 8)>>>(v, vTh, vTl);

    // 3) scores = q @ k^T / 32, per batch; skip fully-masked column blocks
    dim3 gsc(SEQ / BN, SEQ / BM, BATCH);
    mma_gemm_nt<false, false, true, true, false><<<gsc, blk, SMEM_NEED>>>(
        qh, ql, kh, kl, nullptr, lengths, sc, nullptr, nullptr,
        SEQ, SEQ, DIM, 1.f / 32.f, sBD, sBD, sSS);

    // 4) masked softmax -> split weights
    dim3 gsm(SEQ, BATCH);
    softmax_kernel<<<gsm, 256>>>(sc, lengths, sch, scl);

    // 5) attn = w @ vT^T, per batch; truncate K at len (weights are exact zeros)
    dim3 gav(DIM / BN, SEQ / BM, BATCH);
    mma_gemm_nt<false, false, true, false, true><<<gav, blk, SMEM_NEED>>>(
        sch, scl, vTh, vTl, nullptr, lengths, attn, nullptr, nullptr,
        SEQ, DIM, SEQ, 1.f, sSS, sDS, sBD);

    // 6) post = LN(attn + seq), with split
    add_ln_kernel<false, true><<<M, 256>>>(attn, seq, g1, b1, post, posth, postl);

    // 7) h = post @ Wo^T + bo
    mma_gemm_nt<true, false, true, false, false><<<gproj, blk, SMEM_NEED>>>(
        posth, postl, Woh, Wol, bo, nullptr, h, nullptr, nullptr, M, DIM, DIM, 1.f, 0, 0, 0);

    // 8) out = LN(relu(h) + post)
    add_ln_kernel<true, false><<<M, 256>>>(h, post, g2, b2, out, nullptr, nullptr);
}